// round 9
// baseline (speedup 1.0000x reference)
#include <cuda_runtime.h>

// B=1, H=16, S=4096, D=64, fp32, NO softmax.
// (Q K^T) V == Q (K^T V);  K^T V is [64x64] per head -> 64x fewer FLOPs.
// R8: tf32x3 tensor-core GEMMs with the hi/lo split HOISTED to staging time.
// Smem holds pre-split tf32 planes; inner loop = conflict-free LDS + MMA only.
#define HEADS 16
#define SEQ   4096
#define DIM   64
#define NSPLIT 32
#define CHUNK (SEQ / NSPLIT)   // 128 rows per partial block

__device__ __align__(16) float    g_partial[HEADS * NSPLIT * DIM * DIM];  // 8 MB
__device__ __align__(16) unsigned g_Mhi[HEADS * DIM * DIM];               // 256 KB
__device__ __align__(16) unsigned g_Mlo[HEADS * DIM * DIM];               // 256 KB

// ---- tf32 helpers ---------------------------------------------------------
__device__ __forceinline__ void split_tf32(float x, unsigned& hi, unsigned& lo) {
    asm("cvt.rna.tf32.f32 %0, %1;" : "=r"(hi) : "f"(x));
    const float hf = __uint_as_float(hi);
    const float l  = x - hf;
    asm("cvt.rna.tf32.f32 %0, %1;" : "=r"(lo) : "f"(l));
}
__device__ __forceinline__ void split4(float4 x, uint4& hi, uint4& lo) {
    split_tf32(x.x, hi.x, lo.x);
    split_tf32(x.y, hi.y, lo.y);
    split_tf32(x.z, hi.z, lo.z);
    split_tf32(x.w, hi.w, lo.w);
}
__device__ __forceinline__ void mma_tf32(float* d, const unsigned* a, const unsigned* b) {
    asm("mma.sync.aligned.m16n8k8.row.col.f32.tf32.tf32.f32 "
        "{%0,%1,%2,%3}, {%4,%5,%6,%7}, {%8,%9}, {%0,%1,%2,%3};"
        : "+f"(d[0]), "+f"(d[1]), "+f"(d[2]), "+f"(d[3])
        : "r"(a[0]), "r"(a[1]), "r"(a[2]), "r"(a[3]), "r"(b[0]), "r"(b[1]));
}

// ---------------------------------------------------------------------------
// Kernel 1: partial M = K_chunk^T @ V_chunk.  grid = HEADS*NSPLIT, 256 thr.
// 32-row s-tiles; smem holds pre-split tf32 planes (stride 72 == 8 mod 32 ->
// fragment gathers hit banks (8t+g): conflict-free).
// 8 warps: (wid&3) -> d1 block of 16;  (wid>>2) -> d2 block of 32 (nt=4).
// ---------------------------------------------------------------------------
#define KP 72
__global__ __launch_bounds__(256) void ktv_partial(const float* __restrict__ Kp,
                                                   const float* __restrict__ Vp) {
    const int h  = blockIdx.x / NSPLIT;
    const int sp = blockIdx.x % NSPLIT;
    const float* Kh = Kp + ((size_t)h * SEQ + (size_t)sp * CHUNK) * DIM;
    const float* Vh = Vp + ((size_t)h * SEQ + (size_t)sp * CHUNK) * DIM;

    __shared__ __align__(16) unsigned Khi[32][KP], Klo[32][KP];
    __shared__ __align__(16) unsigned Vhi[32][KP], Vlo[32][KP];   // 36.9 KB total

    const int tid  = threadIdx.x;
    const int wid  = tid >> 5;
    const int lane = tid & 31;
    const int g = lane >> 2;      // 0..7
    const int t = lane & 3;       // 0..3
    const int d1_0 = (wid & 3) * 16;
    const int d2_0 = (wid >> 2) * 32;

    float acc[4][4] = {};

    for (int t0 = 0; t0 < CHUNK; t0 += 32) {
        // stage + split 32 rows x 64 floats of K and V (split each elem ONCE)
        #pragma unroll
        for (int i = tid; i < 32 * 16; i += 256) {
            const int r  = i >> 4;
            const int c4 = (i & 15) << 2;
            uint4 hi, lo;
            split4(*(const float4*)&Kh[(size_t)(t0 + r) * DIM + c4], hi, lo);
            *(uint4*)&Khi[r][c4] = hi;
            *(uint4*)&Klo[r][c4] = lo;
            split4(*(const float4*)&Vh[(size_t)(t0 + r) * DIM + c4], hi, lo);
            *(uint4*)&Vhi[r][c4] = hi;
            *(uint4*)&Vlo[r][c4] = lo;
        }
        __syncthreads();

        #pragma unroll
        for (int ks = 0; ks < 32; ks += 8) {
            unsigned ah[4], al[4];
            ah[0] = Khi[ks + t][d1_0 + g];     al[0] = Klo[ks + t][d1_0 + g];
            ah[1] = Khi[ks + t][d1_0 + g + 8]; al[1] = Klo[ks + t][d1_0 + g + 8];
            ah[2] = Khi[ks + t + 4][d1_0 + g]; al[2] = Klo[ks + t + 4][d1_0 + g];
            ah[3] = Khi[ks + t + 4][d1_0 + g + 8]; al[3] = Klo[ks + t + 4][d1_0 + g + 8];
            #pragma unroll
            for (int nt = 0; nt < 4; nt++) {
                const int col = d2_0 + nt * 8 + g;
                unsigned bh[2], bl[2];
                bh[0] = Vhi[ks + t][col];     bl[0] = Vlo[ks + t][col];
                bh[1] = Vhi[ks + t + 4][col]; bl[1] = Vlo[ks + t + 4][col];
                mma_tf32(acc[nt], ah, bh);
                mma_tf32(acc[nt], ah, bl);
                mma_tf32(acc[nt], al, bh);
            }
        }
        __syncthreads();
    }

    float* outp = g_partial + ((size_t)h * NSPLIT + sp) * DIM * DIM;
    #pragma unroll
    for (int nt = 0; nt < 4; nt++) {
        const int col = d2_0 + nt * 8 + 2 * t;
        const int row = d1_0 + g;
        *(float2*)&outp[row * DIM + col]       = make_float2(acc[nt][0], acc[nt][1]);
        *(float2*)&outp[(row + 8) * DIM + col] = make_float2(acc[nt][2], acc[nt][3]);
    }
}

// ---------------------------------------------------------------------------
// Kernel 2: reduce NSPLIT partials, split to tf32 hi/lo planes in GMEM.
// ---------------------------------------------------------------------------
__global__ __launch_bounds__(256) void reduce_m() {
    const int idx = blockIdx.x * 256 + threadIdx.x;   // float4 index
    if (idx >= HEADS * DIM * DIM / 4) return;
    const int h = idx / (DIM * DIM / 4);
    const int e = idx % (DIM * DIM / 4);
    float4 s = make_float4(0.f, 0.f, 0.f, 0.f);
    #pragma unroll
    for (int p = 0; p < NSPLIT; p++) {
        const float4 tv = *(const float4*)&g_partial[(((size_t)h * NSPLIT + p) * DIM * DIM) + e * 4];
        s.x += tv.x; s.y += tv.y; s.z += tv.z; s.w += tv.w;
    }
    uint4 hi, lo;
    split4(s, hi, lo);
    *(uint4*)&g_Mhi[(size_t)idx * 4] = hi;
    *(uint4*)&g_Mlo[(size_t)idx * 4] = lo;
}

// ---------------------------------------------------------------------------
// Kernel 3: out = Q @ M.  Block = 32 q-rows x 64 cols, 256 thr (8 warps).
// Warp tile 16x16 (nt=2): (wid&1) -> row block, (wid>>1) -> col block of 16.
// M comes PRE-SPLIT from gmem into stride-72 planes (conflict-free 8t+g).
// Q staged raw (stride 68 -> conflict-free 4g+t), split per-warp (4 elems/kstep).
// Smem = 36.9 + 8.7 = 45.6 KB (static-limit safe).
// ---------------------------------------------------------------------------
#define QP 68
__global__ __launch_bounds__(256) void qm_gemm(const float* __restrict__ Qp,
                                               float* __restrict__ Op) {
    const int h  = blockIdx.x >> 7;            // 128 blocks per head
    const int r0 = (blockIdx.x & 127) * 32;

    __shared__ __align__(16) unsigned Mhi_s[DIM][KP], Mlo_s[DIM][KP];  // 36.9 KB
    __shared__ __align__(16) float Qs[32][QP];                          // 8.7 KB

    const int tid  = threadIdx.x;
    const int wid  = tid >> 5;
    const int lane = tid & 31;
    const int g = lane >> 2;
    const int t = lane & 3;
    const int rw = (wid & 1) * 16;     // q-row block within 32
    const int c0 = (wid >> 1) * 16;    // out col block of 16

    const float* Qh = Qp + ((size_t)h * SEQ + r0) * DIM;
    const unsigned* MhiG = g_Mhi + (size_t)h * DIM * DIM;
    const unsigned* MloG = g_Mlo + (size_t)h * DIM * DIM;

    // stage M planes (1024 uint4 each) and Q tile (512 float4)
    #pragma unroll
    for (int i = tid; i < DIM * 16; i += 256) {
        const int r  = i >> 4;
        const int c4 = (i & 15) << 2;
        *(uint4*)&Mhi_s[r][c4] = *(const uint4*)&MhiG[r * DIM + c4];
        *(uint4*)&Mlo_s[r][c4] = *(const uint4*)&MloG[r * DIM + c4];
    }
    #pragma unroll
    for (int i = tid; i < 32 * 16; i += 256) {
        const int r  = i >> 4;
        const int c4 = (i & 15) << 2;
        *(float4*)&Qs[r][c4] = *(const float4*)&Qh[(size_t)r * DIM + c4];
    }
    __syncthreads();

    float acc[2][4] = {};

    #pragma unroll
    for (int ks = 0; ks < DIM; ks += 8) {
        unsigned ah[4], al[4];
        split_tf32(Qs[rw + g][ks + t],         ah[0], al[0]);
        split_tf32(Qs[rw + g + 8][ks + t],     ah[1], al[1]);
        split_tf32(Qs[rw + g][ks + t + 4],     ah[2], al[2]);
        split_tf32(Qs[rw + g + 8][ks + t + 4], ah[3], al[3]);
        #pragma unroll
        for (int nt = 0; nt < 2; nt++) {
            const int col = c0 + nt * 8 + g;
            unsigned bh[2], bl[2];
            bh[0] = Mhi_s[ks + t][col];     bl[0] = Mlo_s[ks + t][col];
            bh[1] = Mhi_s[ks + t + 4][col]; bl[1] = Mlo_s[ks + t + 4][col];
            mma_tf32(acc[nt], ah, bh);
            mma_tf32(acc[nt], ah, bl);
            mma_tf32(acc[nt], al, bh);
        }
    }

    float* Oh = Op + ((size_t)h * SEQ + r0) * DIM;
    #pragma unroll
    for (int nt = 0; nt < 2; nt++) {
        const int col = c0 + nt * 8 + 2 * t;
        const int row = rw + g;
        *(float2*)&Oh[(size_t)row * DIM + col]       = make_float2(acc[nt][0], acc[nt][1]);
        *(float2*)&Oh[(size_t)(row + 8) * DIM + col] = make_float2(acc[nt][2], acc[nt][3]);
    }
}

// ---------------------------------------------------------------------------
extern "C" void kernel_launch(void* const* d_in, const int* in_sizes, int n_in,
                              void* d_out, int out_size) {
    const float* q = (const float*)d_in[0];
    const float* k = (const float*)d_in[1];
    const float* v = (const float*)d_in[2];
    float* out = (float*)d_out;

    ktv_partial<<<HEADS * NSPLIT, 256>>>(k, v);
    reduce_m<<<(HEADS * DIM * DIM / 4 + 255) / 256, 256>>>();
    qm_gemm<<<HEADS * (SEQ / 32), 256>>>(q, out);
}

// round 11
// speedup vs baseline: 1.0571x; 1.0571x over previous
#include <cuda_runtime.h>

// B=1, H=16, S=4096, D=64, fp32, NO softmax.
// (Q K^T) V == Q (K^T V);  K^T V is [64x64] per head -> 64x fewer FLOPs.
// R10: tf32x3 tensor-core GEMMs, pre-split hi/lo planes in smem.
//  - ktv: software-pipelined staging (register-buffer next tile over MMA)
//  - qm : 128-row blocks (4x fewer M-plane reloads), dynamic smem
#define HEADS 16
#define SEQ   4096
#define DIM   64
#define NSPLIT 32
#define CHUNK (SEQ / NSPLIT)   // 128 rows per partial block

__device__ __align__(16) float    g_partial[HEADS * NSPLIT * DIM * DIM];  // 8 MB
__device__ __align__(16) unsigned g_Mhi[HEADS * DIM * DIM];               // 256 KB
__device__ __align__(16) unsigned g_Mlo[HEADS * DIM * DIM];               // 256 KB

// ---- tf32 helpers ---------------------------------------------------------
__device__ __forceinline__ void split_tf32(float x, unsigned& hi, unsigned& lo) {
    asm("cvt.rna.tf32.f32 %0, %1;" : "=r"(hi) : "f"(x));
    const float hf = __uint_as_float(hi);
    const float l  = x - hf;
    asm("cvt.rna.tf32.f32 %0, %1;" : "=r"(lo) : "f"(l));
}
__device__ __forceinline__ void split4(float4 x, uint4& hi, uint4& lo) {
    split_tf32(x.x, hi.x, lo.x);
    split_tf32(x.y, hi.y, lo.y);
    split_tf32(x.z, hi.z, lo.z);
    split_tf32(x.w, hi.w, lo.w);
}
__device__ __forceinline__ void mma_tf32(float* d, const unsigned* a, const unsigned* b) {
    asm("mma.sync.aligned.m16n8k8.row.col.f32.tf32.tf32.f32 "
        "{%0,%1,%2,%3}, {%4,%5,%6,%7}, {%8,%9}, {%0,%1,%2,%3};"
        : "+f"(d[0]), "+f"(d[1]), "+f"(d[2]), "+f"(d[3])
        : "r"(a[0]), "r"(a[1]), "r"(a[2]), "r"(a[3]), "r"(b[0]), "r"(b[1]));
}

// ---------------------------------------------------------------------------
// Kernel 1: partial M = K_chunk^T @ V_chunk.  grid = HEADS*NSPLIT, 256 thr.
// Pre-split tf32 planes, stride 72 (==8 mod 32 -> (8t+g) gathers conflict-free).
// 8 warps: (wid&3) -> d1 block of 16;  (wid>>2) -> d2 block of 32 (nt=4).
// Staging is SW-pipelined: next 32-row tile loads into regs during MMA.
// ---------------------------------------------------------------------------
#define KP 72
__global__ __launch_bounds__(256) void ktv_partial(const float* __restrict__ Kp,
                                                   const float* __restrict__ Vp) {
    const int h  = blockIdx.x / NSPLIT;
    const int sp = blockIdx.x % NSPLIT;
    const float* Kh = Kp + ((size_t)h * SEQ + (size_t)sp * CHUNK) * DIM;
    const float* Vh = Vp + ((size_t)h * SEQ + (size_t)sp * CHUNK) * DIM;

    __shared__ __align__(16) unsigned Khi[32][KP], Klo[32][KP];
    __shared__ __align__(16) unsigned Vhi[32][KP], Vlo[32][KP];   // 36.9 KB

    const int tid  = threadIdx.x;
    const int wid  = tid >> 5;
    const int lane = tid & 31;
    const int g = lane >> 2;      // 0..7
    const int t = lane & 3;       // 0..3
    const int d1_0 = (wid & 3) * 16;
    const int d2_0 = (wid >> 2) * 32;

    // per-thread staging slots: i = tid + j*256 -> row i>>4, col4 (i&15)<<2
    const int sr0 = tid >> 4,          sc0 = (tid & 15) << 2;
    const int sr1 = (tid + 256) >> 4,  sc1 = sc0;

    float4 kbuf[2], vbuf[2];

    float acc[4][4] = {};

    // prologue: load + split tile 0
    kbuf[0] = *(const float4*)&Kh[(size_t)sr0 * DIM + sc0];
    vbuf[0] = *(const float4*)&Vh[(size_t)sr0 * DIM + sc0];
    kbuf[1] = *(const float4*)&Kh[(size_t)sr1 * DIM + sc1];
    vbuf[1] = *(const float4*)&Vh[(size_t)sr1 * DIM + sc1];
    {
        uint4 hi, lo;
        split4(kbuf[0], hi, lo); *(uint4*)&Khi[sr0][sc0] = hi; *(uint4*)&Klo[sr0][sc0] = lo;
        split4(vbuf[0], hi, lo); *(uint4*)&Vhi[sr0][sc0] = hi; *(uint4*)&Vlo[sr0][sc0] = lo;
        split4(kbuf[1], hi, lo); *(uint4*)&Khi[sr1][sc1] = hi; *(uint4*)&Klo[sr1][sc1] = lo;
        split4(vbuf[1], hi, lo); *(uint4*)&Vhi[sr1][sc1] = hi; *(uint4*)&Vlo[sr1][sc1] = lo;
    }
    __syncthreads();

    #pragma unroll
    for (int ph = 0; ph < CHUNK / 32; ph++) {
        // issue loads for next tile early (overlap with MMA below)
        if (ph < CHUNK / 32 - 1) {
            const int t0 = (ph + 1) * 32;
            kbuf[0] = *(const float4*)&Kh[(size_t)(t0 + sr0) * DIM + sc0];
            vbuf[0] = *(const float4*)&Vh[(size_t)(t0 + sr0) * DIM + sc0];
            kbuf[1] = *(const float4*)&Kh[(size_t)(t0 + sr1) * DIM + sc1];
            vbuf[1] = *(const float4*)&Vh[(size_t)(t0 + sr1) * DIM + sc1];
        }

        #pragma unroll
        for (int ks = 0; ks < 32; ks += 8) {
            unsigned ah[4], al[4];
            ah[0] = Khi[ks + t][d1_0 + g];         al[0] = Klo[ks + t][d1_0 + g];
            ah[1] = Khi[ks + t][d1_0 + g + 8];     al[1] = Klo[ks + t][d1_0 + g + 8];
            ah[2] = Khi[ks + t + 4][d1_0 + g];     al[2] = Klo[ks + t + 4][d1_0 + g];
            ah[3] = Khi[ks + t + 4][d1_0 + g + 8]; al[3] = Klo[ks + t + 4][d1_0 + g + 8];
            #pragma unroll
            for (int nt = 0; nt < 4; nt++) {
                const int col = d2_0 + nt * 8 + g;
                unsigned bh[2], bl[2];
                bh[0] = Vhi[ks + t][col];     bl[0] = Vlo[ks + t][col];
                bh[1] = Vhi[ks + t + 4][col]; bl[1] = Vlo[ks + t + 4][col];
                mma_tf32(acc[nt], ah, bh);
                mma_tf32(acc[nt], ah, bl);
                mma_tf32(acc[nt], al, bh);
            }
        }
        __syncthreads();   // MMA done before smem overwrite

        if (ph < CHUNK / 32 - 1) {
            uint4 hi, lo;
            split4(kbuf[0], hi, lo); *(uint4*)&Khi[sr0][sc0] = hi; *(uint4*)&Klo[sr0][sc0] = lo;
            split4(vbuf[0], hi, lo); *(uint4*)&Vhi[sr0][sc0] = hi; *(uint4*)&Vlo[sr0][sc0] = lo;
            split4(kbuf[1], hi, lo); *(uint4*)&Khi[sr1][sc1] = hi; *(uint4*)&Klo[sr1][sc1] = lo;
            split4(vbuf[1], hi, lo); *(uint4*)&Vhi[sr1][sc1] = hi; *(uint4*)&Vlo[sr1][sc1] = lo;
            __syncthreads();
        }
    }

    float* outp = g_partial + ((size_t)h * NSPLIT + sp) * DIM * DIM;
    #pragma unroll
    for (int nt = 0; nt < 4; nt++) {
        const int col = d2_0 + nt * 8 + 2 * t;
        const int row = d1_0 + g;
        *(float2*)&outp[row * DIM + col]       = make_float2(acc[nt][0], acc[nt][1]);
        *(float2*)&outp[(row + 8) * DIM + col] = make_float2(acc[nt][2], acc[nt][3]);
    }
}

// ---------------------------------------------------------------------------
// Kernel 2: reduce NSPLIT partials, split to tf32 hi/lo planes in GMEM.
// ---------------------------------------------------------------------------
__global__ __launch_bounds__(256) void reduce_m() {
    const int idx = blockIdx.x * 256 + threadIdx.x;   // float4 index
    if (idx >= HEADS * DIM * DIM / 4) return;
    const int h = idx / (DIM * DIM / 4);
    const int e = idx % (DIM * DIM / 4);
    float4 s = make_float4(0.f, 0.f, 0.f, 0.f);
    #pragma unroll
    for (int p = 0; p < NSPLIT; p++) {
        const float4 tv = *(const float4*)&g_partial[(((size_t)h * NSPLIT + p) * DIM * DIM) + e * 4];
        s.x += tv.x; s.y += tv.y; s.z += tv.z; s.w += tv.w;
    }
    uint4 hi, lo;
    split4(s, hi, lo);
    *(uint4*)&g_Mhi[(size_t)idx * 4] = hi;
    *(uint4*)&g_Mlo[(size_t)idx * 4] = lo;
}

// ---------------------------------------------------------------------------
// Kernel 3: out = Q @ M.  Block = 128 q-rows x 64 cols, 256 thr (8 warps).
// Warps 4x2: (wid&3) -> 32-row group, (wid>>2) -> 32-col group.
// Warp tile 32x32: mt=2 (16-row mmas), nt=4 (8-col mmas), 24 MMA/k-step.
// M planes pre-split (stride 72, conflict-free); Q raw (stride 68,
// (4g+t) gathers conflict-free), split per-thread in-loop (8 elems/k-step).
// Dynamic smem: Mhi/Mlo 36.9 KB + Qs 34.8 KB = 71.7 KB.
// ---------------------------------------------------------------------------
#define QP 68
#define QROWS 128
__global__ __launch_bounds__(256) void qm_gemm(const float* __restrict__ Qp,
                                               float* __restrict__ Op) {
    extern __shared__ __align__(16) char smem_raw[];
    unsigned (*Mhi_s)[KP] = (unsigned (*)[KP])smem_raw;
    unsigned (*Mlo_s)[KP] = (unsigned (*)[KP])(smem_raw + DIM * KP * 4);
    float    (*Qs)[QP]    = (float    (*)[QP])(smem_raw + 2 * DIM * KP * 4);

    const int h  = blockIdx.x >> 5;            // 32 blocks per head
    const int r0 = (blockIdx.x & 31) * QROWS;

    const int tid  = threadIdx.x;
    const int wid  = tid >> 5;
    const int lane = tid & 31;
    const int g = lane >> 2;
    const int t = lane & 3;
    const int rw = (wid & 3) * 32;     // q-row group (of 32) within 128
    const int c0 = (wid >> 2) * 32;    // out col group of 32

    const float* Qh = Qp + ((size_t)h * SEQ + r0) * DIM;
    const unsigned* MhiG = g_Mhi + (size_t)h * DIM * DIM;
    const unsigned* MloG = g_Mlo + (size_t)h * DIM * DIM;

    // stage M planes (1024 uint4 each)
    #pragma unroll
    for (int i = tid; i < DIM * 16; i += 256) {
        const int r  = i >> 4;
        const int c4 = (i & 15) << 2;
        *(uint4*)&Mhi_s[r][c4] = *(const uint4*)&MhiG[r * DIM + c4];
        *(uint4*)&Mlo_s[r][c4] = *(const uint4*)&MloG[r * DIM + c4];
    }
    // stage Q tile (2048 float4)
    #pragma unroll
    for (int i = tid; i < QROWS * 16; i += 256) {
        const int r  = i >> 4;
        const int c4 = (i & 15) << 2;
        *(float4*)&Qs[r][c4] = *(const float4*)&Qh[(size_t)r * DIM + c4];
    }
    __syncthreads();

    float acc[2][4][4] = {};

    #pragma unroll
    for (int ks = 0; ks < DIM; ks += 8) {
        unsigned ah[2][4], al[2][4];
        #pragma unroll
        for (int mt = 0; mt < 2; mt++) {
            const int row = rw + mt * 16;
            split_tf32(Qs[row + g][ks + t],         ah[mt][0], al[mt][0]);
            split_tf32(Qs[row + g + 8][ks + t],     ah[mt][1], al[mt][1]);
            split_tf32(Qs[row + g][ks + t + 4],     ah[mt][2], al[mt][2]);
            split_tf32(Qs[row + g + 8][ks + t + 4], ah[mt][3], al[mt][3]);
        }
        #pragma unroll
        for (int nt = 0; nt < 4; nt++) {
            const int col = c0 + nt * 8 + g;
            unsigned bh[2], bl[2];
            bh[0] = Mhi_s[ks + t][col];     bl[0] = Mlo_s[ks + t][col];
            bh[1] = Mhi_s[ks + t + 4][col]; bl[1] = Mlo_s[ks + t + 4][col];
            #pragma unroll
            for (int mt = 0; mt < 2; mt++) {
                mma_tf32(acc[mt][nt], ah[mt], bh);
                mma_tf32(acc[mt][nt], ah[mt], bl);
                mma_tf32(acc[mt][nt], al[mt], bh);
            }
        }
    }

    float* Oh = Op + ((size_t)h * SEQ + r0) * DIM;
    #pragma unroll
    for (int mt = 0; mt < 2; mt++) {
        #pragma unroll
        for (int nt = 0; nt < 4; nt++) {
            const int col = c0 + nt * 8 + 2 * t;
            const int row = rw + mt * 16 + g;
            *(float2*)&Oh[(size_t)row * DIM + col]       = make_float2(acc[mt][nt][0], acc[mt][nt][1]);
            *(float2*)&Oh[(size_t)(row + 8) * DIM + col] = make_float2(acc[mt][nt][2], acc[mt][nt][3]);
        }
    }
}

// ---------------------------------------------------------------------------
extern "C" void kernel_launch(void* const* d_in, const int* in_sizes, int n_in,
                              void* d_out, int out_size) {
    const float* q = (const float*)d_in[0];
    const float* k = (const float*)d_in[1];
    const float* v = (const float*)d_in[2];
    float* out = (float*)d_out;

    const int qm_smem = (2 * DIM * KP + QROWS * QP) * 4;   // 71.7 KB
    static int attr_done = 0;   // idempotent attribute set (not a work guard)
    if (!attr_done) {
        cudaFuncSetAttribute(qm_gemm, cudaFuncAttributeMaxDynamicSharedMemorySize, qm_smem);
        attr_done = 1;
    }

    ktv_partial<<<HEADS * NSPLIT, 256>>>(k, v);
    reduce_m<<<(HEADS * DIM * DIM / 4 + 255) / 256, 256>>>();
    qm_gemm<<<HEADS * (SEQ / QROWS), 256, qm_smem>>>(q, out);
}